// round 10
// baseline (speedup 1.0000x reference)
#include <cuda_runtime.h>
#include <cstdint>

// Problem constants (fixed by the dataset)
#define BB 4
#define NN 10000
#define EE 163840
#define NREG 2000
#define DIN 64
#define DEN 16
#define NEG_SLOPE 0.2f
#define EPT 4               // edges per thread in k_edge (EE % (256*EPT) == 0)

// ---------------- static device scratch (no allocations allowed) -------------
__device__ float g_h[BB * NN * DEN];              // h = x @ W
__device__ float g_as[BB * NN];                   // h @ att_src
__device__ float g_ad[BB * NN];                   // h @ att_dst
__device__ float g_den[BB * NN];                  // softmax denominator per dst
__device__ __align__(16) float g_rep[BB * NN * DEN]; // unnormalized ex-weighted sums
__device__ int   g_rowstart[BB * (NREG + 1)];     // CSR row starts over sorted src
__device__ float g_ce;                            // lin_edge . att_edge (scalar)

// ---------------- K1: per-node h = xW, a_s, a_d; zero den/rep; g_ce ----------
__global__ void k_node(const float* __restrict__ x, const float* __restrict__ W,
                       const float* __restrict__ att_s, const float* __restrict__ att_d,
                       const float* __restrict__ lin_edge, const float* __restrict__ att_edge) {
    __shared__ float Ws[DIN * DEN];
    for (int i = threadIdx.x; i < DIN * DEN; i += blockDim.x) Ws[i] = W[i];
    __syncthreads();

    int t = blockIdx.x * blockDim.x + threadIdx.x;
    if (t == 0) {
        float c = 0.0f;
#pragma unroll
        for (int j = 0; j < DEN; j++) c += lin_edge[j] * att_edge[j];
        g_ce = c;
    }
    if (t >= BB * NN) return;

    // zero the accumulators the edge pass will atomically update
    g_den[t] = 0.0f;
    float4* rz = reinterpret_cast<float4*>(g_rep + (size_t)t * DEN);
    float4 z4 = make_float4(0.f, 0.f, 0.f, 0.f);
#pragma unroll
    for (int u = 0; u < DEN / 4; u++) rz[u] = z4;

    const float4* xr = reinterpret_cast<const float4*>(x + (size_t)t * DIN);
    float acc[DEN];
#pragma unroll
    for (int c = 0; c < DEN; c++) acc[c] = 0.0f;

#pragma unroll
    for (int k4 = 0; k4 < DIN / 4; k4++) {
        float4 v = xr[k4];
        const float* w0 = &Ws[(k4 * 4 + 0) * DEN];
        const float* w1 = &Ws[(k4 * 4 + 1) * DEN];
        const float* w2 = &Ws[(k4 * 4 + 2) * DEN];
        const float* w3 = &Ws[(k4 * 4 + 3) * DEN];
#pragma unroll
        for (int c = 0; c < DEN; c++)
            acc[c] += v.x * w0[c] + v.y * w1[c] + v.z * w2[c] + v.w * w3[c];
    }

    float as = 0.0f, ad = 0.0f;
#pragma unroll
    for (int c = 0; c < DEN; c++) {
        as += acc[c] * __ldg(&att_s[c]);
        ad += acc[c] * __ldg(&att_d[c]);
    }

    float4* hp = reinterpret_cast<float4*>(g_h + (size_t)t * DEN);
#pragma unroll
    for (int u = 0; u < DEN / 4; u++)
        hp[u] = make_float4(acc[u * 4 + 0], acc[u * 4 + 1], acc[u * 4 + 2], acc[u * 4 + 3]);
    g_as[t] = as;
    g_ad[t] = ad;
}

// ---------------- K2 (fused): 4 edges/thread; ex; atomic den; scatter --------
__device__ __forceinline__ void red_add_v4(float* p, float a, float b2, float c, float d) {
    asm volatile("red.global.add.v4.f32 [%0], {%1, %2, %3, %4};"
                 :: "l"(p), "f"(a), "f"(b2), "f"(c), "f"(d) : "memory");
}

__global__ void k_edge_fused(const int* __restrict__ ei, const float* __restrict__ ea) {
    int b = blockIdx.y;
    int e0 = (blockIdx.x * blockDim.x + threadIdx.x) * EPT;
    if (e0 >= EE) return;

    const int* srcp = ei + (size_t)b * 2 * EE;
    const int* dstp = srcp + EE;
    int4 s4 = *reinterpret_cast<const int4*>(srcp + e0);
    int4 d4 = *reinterpret_cast<const int4*>(dstp + e0);
    float4 a4 = *reinterpret_cast<const float4*>(ea + (size_t)b * EE + e0);
    float ce = g_ce;

    int   sv[EPT] = {s4.x, s4.y, s4.z, s4.w};
    int   dv[EPT] = {d4.x, d4.y, d4.z, d4.w};
    float av[EPT] = {a4.x, a4.y, a4.z, a4.w};

    // CSR row starts over sorted src (every regulator guaranteed covered)
    if (e0 == 0) {
        g_rowstart[b * (NREG + 1) + NREG] = EE;
        g_rowstart[b * (NREG + 1) + sv[0]] = 0;
    } else if (srcp[e0 - 1] != sv[0]) {
        g_rowstart[b * (NREG + 1) + sv[0]] = e0;
    }
#pragma unroll
    for (int j = 1; j < EPT; j++)
        if (sv[j - 1] != sv[j]) g_rowstart[b * (NREG + 1) + sv[j]] = e0 + j;

    float ex[EPT];
#pragma unroll
    for (int j = 0; j < EPT; j++) {
        float v = g_as[b * NN + sv[j]] + g_ad[b * NN + dv[j]] + ce * av[j];
        v = (v > 0.0f) ? v : NEG_SLOPE * v;
        ex[j] = __expf(v);
    }

#pragma unroll
    for (int j = 0; j < EPT; j++) {
        atomicAdd(&g_den[b * NN + dv[j]], ex[j]);
        const float4* hp = reinterpret_cast<const float4*>(g_h + (size_t)(b * NN + sv[j]) * DEN);
        float* rp = g_rep + (size_t)(b * NN + dv[j]) * DEN;
#pragma unroll
        for (int u = 0; u < DEN / 4; u++) {
            float4 h4 = hp[u];
            red_add_v4(rp + u * 4, ex[j] * h4.x, ex[j] * h4.y, ex[j] * h4.z, ex[j] * h4.w);
        }
    }
}

// ---------------- K3: warp-per-regulator pool with on-the-fly normalize ------
#define POOL_WARPS 8
#define HSLOTS 256          // power of 2, >> max edges per regulator (~130)
#define DUPFLAG 0x40000000

__global__ void k_pool(const int* __restrict__ ei, const float* __restrict__ bias,
                       float* __restrict__ out) {
    __shared__ int hkey[POOL_WARPS][HSLOTS];
    __shared__ int list[POOL_WARPS][HSLOTS];
    __shared__ int lcount[POOL_WARPS];

    int warp = threadIdx.x >> 5;
    int lane = threadIdx.x & 31;
    int g = blockIdx.x * POOL_WARPS + warp;
    if (g >= BB * NREG) return;
    int b = g / NREG;
    int i = g - b * NREG;

    int s = g_rowstart[b * (NREG + 1) + i];
    int e = g_rowstart[b * (NREG + 1) + i + 1];
    int k = e - s;
    const int* dstp = ei + (size_t)b * 2 * EE + EE + s;

    // init hash
    for (int j = lane; j < HSLOTS; j += 32) hkey[warp][j] = -1;
    if (lane == 0) lcount[warp] = 0;
    __syncwarp();

    // insert all dsts; flag duplicates (rare: E[dups] ~ 0.34/regulator)
    for (int j = lane; j < k; j += 32) {
        int d = dstp[j];
        unsigned slot = ((unsigned)d * 2654435761u >> 16) & (HSLOTS - 1);
        for (int probe = 0; probe < HSLOTS; probe++) {
            int prev = atomicCAS(&hkey[warp][slot], -1, d);
            if (prev == -1) break;                         // claimed
            if ((prev & ~DUPFLAG) == d) {                  // same key -> duplicate
                if (!(prev & DUPFLAG)) atomicOr(&hkey[warp][slot], DUPFLAG);
                break;
            }
            slot = (slot + 1) & (HSLOTS - 1);
        }
    }
    __syncwarp();

    // compact singleton keys (present, not flagged)
    for (int j = lane; j < HSLOTS; j += 32) {
        int h = hkey[warp][j];
        if (h >= 0 && !(h & DUPFLAG)) {
            int p = atomicAdd(&lcount[warp], 1);
            list[warp][p] = h;
        }
    }
    __syncwarp();
    int m = lcount[warp];

    // cooperative gather with on-the-fly normalize + bias:
    // 4 lanes per rep row, each owning one float4 chunk
    int chunk = lane & 3;
    float4 bchunk = reinterpret_cast<const float4*>(bias)[chunk];
    float4 acc = make_float4(0.f, 0.f, 0.f, 0.f);
    for (int idx = lane >> 2; idx < m; idx += 8) {
        int d = list[warp][idx];
        float den = g_den[b * NN + d];
        float inv = (den > 0.0f) ? __frcp_rn(den) : 0.0f;
        const float4* rp = reinterpret_cast<const float4*>(g_rep + (size_t)(b * NN + d) * DEN);
        float4 r = rp[chunk];
        acc.x += r.x * inv + bchunk.x;
        acc.y += r.y * inv + bchunk.y;
        acc.z += r.z * inv + bchunk.z;
        acc.w += r.w * inv + bchunk.w;
    }
    // reduce across the 8 lanes sharing each chunk id (strides 16, 8, 4)
#pragma unroll
    for (int off = 16; off >= 4; off >>= 1) {
        acc.x += __shfl_down_sync(0xFFFFFFFFu, acc.x, off);
        acc.y += __shfl_down_sync(0xFFFFFFFFu, acc.y, off);
        acc.z += __shfl_down_sync(0xFFFFFFFFu, acc.z, off);
        acc.w += __shfl_down_sync(0xFFFFFFFFu, acc.w, off);
    }

    if (lane < 4) {
        // regulator i == node i; normalize its row on the fly too
        float deni = g_den[b * NN + i];
        float invi = (deni > 0.0f) ? __frcp_rn(deni) : 0.0f;
        const float4* rr = reinterpret_cast<const float4*>(g_rep + (size_t)(b * NN + i) * DEN);
        float4 rv = rr[lane];   // chunk == lane for lane<4
        rv.x = rv.x * invi + bchunk.x;
        rv.y = rv.y * invi + bchunk.y;
        rv.z = rv.z * invi + bchunk.z;
        rv.w = rv.w * invi + bchunk.w;
        float4* op = reinterpret_cast<float4*>(out + (size_t)(b * NREG + i) * DEN);
        op[lane] = make_float4(rv.x * acc.x, rv.y * acc.y, rv.z * acc.z, rv.w * acc.w);
    }
}

// ---------------- launch ------------------------------------------------------
extern "C" void kernel_launch(void* const* d_in, const int* in_sizes, int n_in,
                              void* d_out, int out_size) {
    const float* fea      = (const float*)d_in[0];   // [B,N,64]
    const int*   ei       = (const int*)d_in[1];     // [B,2,E]
    const float* ea       = (const float*)d_in[2];   // [B,E,1]
    const float* W        = (const float*)d_in[3];   // [64,16]
    const float* att_src  = (const float*)d_in[4];   // [16]
    const float* att_dst  = (const float*)d_in[5];   // [16]
    const float* lin_edge = (const float*)d_in[6];   // [1,16]
    const float* att_edge = (const float*)d_in[7];   // [16]
    const float* bias     = (const float*)d_in[8];   // [16]
    float* out = (float*)d_out;                      // [B,NREG,16]

    (void)in_sizes; (void)n_in; (void)out_size;

    {
        int tot = BB * NN;
        k_node<<<(tot + 255) / 256, 256>>>(fea, W, att_src, att_dst, lin_edge, att_edge);
    }
    {
        dim3 grid(EE / (256 * EPT), BB);
        k_edge_fused<<<grid, 256>>>(ei, ea);
    }
    {
        int tot = BB * NREG;
        k_pool<<<(tot + POOL_WARPS - 1) / POOL_WARPS, POOL_WARPS * 32>>>(ei, bias, out);
    }
}

// round 11
// speedup vs baseline: 1.0492x; 1.0492x over previous
#include <cuda_runtime.h>
#include <cstdint>

// Problem constants (fixed by the dataset)
#define BB 4
#define NN 10000
#define EE 163840
#define NREG 2000
#define DIN 64
#define DEN 16
#define NEG_SLOPE 0.2f

// ---------------- static device scratch (no allocations allowed) -------------
__device__ float g_h[BB * NN * DEN];              // h = x @ W
__device__ float g_as[BB * NN];                   // h @ att_src
__device__ float g_ad[BB * NN];                   // h @ att_dst
__device__ float g_den[BB * NN];                  // softmax denominator per dst
__device__ __align__(16) float g_rep[BB * NN * DEN]; // unnormalized ex-weighted sums
__device__ int   g_rowstart[BB * (NREG + 1)];     // CSR row starts over sorted src
__device__ float g_ce;                            // lin_edge . att_edge (scalar)

// ---------------- K1: 4 threads/node: h = xW, a_s, a_d; zero den/rep ---------
__global__ void k_node(const float* __restrict__ x, const float* __restrict__ W,
                       const float* __restrict__ att_s, const float* __restrict__ att_d,
                       const float* __restrict__ lin_edge, const float* __restrict__ att_edge) {
    __shared__ float Ws[DIN * DEN];
    for (int i = threadIdx.x; i < DIN * DEN; i += blockDim.x) Ws[i] = W[i];
    __syncthreads();

    int t = blockIdx.x * blockDim.x + threadIdx.x;
    if (t == 0) {
        float c = 0.0f;
#pragma unroll
        for (int j = 0; j < DEN; j++) c += lin_edge[j] * att_edge[j];
        g_ce = c;
    }
    if (t >= BB * NN * 4) return;
    int node = t >> 2;       // 0 .. BB*NN-1
    int chunk = t & 3;       // which float4 of the 16 output channels

    if (chunk == 0) g_den[node] = 0.0f;
    reinterpret_cast<float4*>(g_rep + (size_t)node * DEN)[chunk] =
        make_float4(0.f, 0.f, 0.f, 0.f);

    const float4* xr = reinterpret_cast<const float4*>(x + (size_t)node * DIN);
    float a0 = 0.f, a1 = 0.f, a2 = 0.f, a3 = 0.f;
    int cbase = chunk * 4;

#pragma unroll
    for (int k4 = 0; k4 < DIN / 4; k4++) {
        float4 v = xr[k4];   // quad-lanes broadcast the same row
        const float* w0 = &Ws[(k4 * 4 + 0) * DEN + cbase];
        const float* w1 = &Ws[(k4 * 4 + 1) * DEN + cbase];
        const float* w2 = &Ws[(k4 * 4 + 2) * DEN + cbase];
        const float* w3 = &Ws[(k4 * 4 + 3) * DEN + cbase];
        a0 += v.x * w0[0] + v.y * w1[0] + v.z * w2[0] + v.w * w3[0];
        a1 += v.x * w0[1] + v.y * w1[1] + v.z * w2[1] + v.w * w3[1];
        a2 += v.x * w0[2] + v.y * w1[2] + v.z * w2[2] + v.w * w3[2];
        a3 += v.x * w0[3] + v.y * w1[3] + v.z * w2[3] + v.w * w3[3];
    }

    // partial attention dots over this thread's 4 channels, combined in-quad
    float as = a0 * __ldg(&att_s[cbase + 0]) + a1 * __ldg(&att_s[cbase + 1])
             + a2 * __ldg(&att_s[cbase + 2]) + a3 * __ldg(&att_s[cbase + 3]);
    float ad = a0 * __ldg(&att_d[cbase + 0]) + a1 * __ldg(&att_d[cbase + 1])
             + a2 * __ldg(&att_d[cbase + 2]) + a3 * __ldg(&att_d[cbase + 3]);
    as += __shfl_xor_sync(0xFFFFFFFFu, as, 1);
    as += __shfl_xor_sync(0xFFFFFFFFu, as, 2);
    ad += __shfl_xor_sync(0xFFFFFFFFu, ad, 1);
    ad += __shfl_xor_sync(0xFFFFFFFFu, ad, 2);

    reinterpret_cast<float4*>(g_h + (size_t)node * DEN)[chunk] =
        make_float4(a0, a1, a2, a3);
    if (chunk == 0) {
        g_as[node] = as;
        g_ad[node] = ad;
    }
}

// ---------------- K2 (fused): per-edge ex; atomic den; scatter ex*h[src] -----
__device__ __forceinline__ void red_add_v4(float* p, float a, float b2, float c, float d) {
    asm volatile("red.global.add.v4.f32 [%0], {%1, %2, %3, %4};"
                 :: "l"(p), "f"(a), "f"(b2), "f"(c), "f"(d) : "memory");
}

__global__ void k_edge_fused(const int* __restrict__ ei, const float* __restrict__ ea) {
    int b = blockIdx.y;
    int e = blockIdx.x * blockDim.x + threadIdx.x;
    if (e >= EE) return;
    const int* srcp = ei + (size_t)b * 2 * EE;
    const int* dstp = srcp + EE;
    int s = srcp[e];
    int d = dstp[e];

    float v = g_as[b * NN + s] + g_ad[b * NN + d] + g_ce * ea[(size_t)b * EE + e];
    v = (v > 0.0f) ? v : NEG_SLOPE * v;
    float ex = __expf(v);

    atomicAdd(&g_den[b * NN + d], ex);

    const float4* hp = reinterpret_cast<const float4*>(g_h + (size_t)(b * NN + s) * DEN);
    float* rp = g_rep + (size_t)(b * NN + d) * DEN;
#pragma unroll
    for (int u = 0; u < DEN / 4; u++) {
        float4 h4 = hp[u];
        red_add_v4(rp + u * 4, ex * h4.x, ex * h4.y, ex * h4.z, ex * h4.w);
    }

    // CSR row starts over sorted src (every regulator guaranteed covered)
    if (e == 0) {
        g_rowstart[b * (NREG + 1) + NREG] = EE;
        g_rowstart[b * (NREG + 1) + s] = 0;
    } else if (srcp[e - 1] != s) {
        g_rowstart[b * (NREG + 1) + s] = e;
    }
}

// ---------------- K3: warp-per-regulator pool with on-the-fly normalize ------
#define POOL_WARPS 8
#define HSLOTS 256          // power of 2, >> max edges per regulator (~130)
#define DUPFLAG 0x40000000

__global__ void k_pool(const int* __restrict__ ei, const float* __restrict__ bias,
                       float* __restrict__ out) {
    __shared__ int hkey[POOL_WARPS][HSLOTS];
    __shared__ int list[POOL_WARPS][HSLOTS];
    __shared__ int lcount[POOL_WARPS];

    int warp = threadIdx.x >> 5;
    int lane = threadIdx.x & 31;
    int g = blockIdx.x * POOL_WARPS + warp;
    if (g >= BB * NREG) return;
    int b = g / NREG;
    int i = g - b * NREG;

    int s = g_rowstart[b * (NREG + 1) + i];
    int e = g_rowstart[b * (NREG + 1) + i + 1];
    int k = e - s;
    const int* dstp = ei + (size_t)b * 2 * EE + EE + s;

    // init hash
    for (int j = lane; j < HSLOTS; j += 32) hkey[warp][j] = -1;
    if (lane == 0) lcount[warp] = 0;
    __syncwarp();

    // insert all dsts; flag duplicates (rare: E[dups] ~ 0.34/regulator)
    for (int j = lane; j < k; j += 32) {
        int d = dstp[j];
        unsigned slot = ((unsigned)d * 2654435761u >> 16) & (HSLOTS - 1);
        for (int probe = 0; probe < HSLOTS; probe++) {
            int prev = atomicCAS(&hkey[warp][slot], -1, d);
            if (prev == -1) break;                         // claimed
            if ((prev & ~DUPFLAG) == d) {                  // same key -> duplicate
                if (!(prev & DUPFLAG)) atomicOr(&hkey[warp][slot], DUPFLAG);
                break;
            }
            slot = (slot + 1) & (HSLOTS - 1);
        }
    }
    __syncwarp();

    // compact singleton keys (present, not flagged)
    for (int j = lane; j < HSLOTS; j += 32) {
        int h = hkey[warp][j];
        if (h >= 0 && !(h & DUPFLAG)) {
            int p = atomicAdd(&lcount[warp], 1);
            list[warp][p] = h;
        }
    }
    __syncwarp();
    int m = lcount[warp];

    // cooperative gather with on-the-fly normalize + bias:
    // 4 lanes per rep row, each owning one float4 chunk
    int chunk = lane & 3;
    float4 bchunk = reinterpret_cast<const float4*>(bias)[chunk];
    float4 acc = make_float4(0.f, 0.f, 0.f, 0.f);
    for (int idx = lane >> 2; idx < m; idx += 8) {
        int d = list[warp][idx];
        float den = g_den[b * NN + d];
        float inv = (den > 0.0f) ? __frcp_rn(den) : 0.0f;
        const float4* rp = reinterpret_cast<const float4*>(g_rep + (size_t)(b * NN + d) * DEN);
        float4 r = rp[chunk];
        acc.x += r.x * inv + bchunk.x;
        acc.y += r.y * inv + bchunk.y;
        acc.z += r.z * inv + bchunk.z;
        acc.w += r.w * inv + bchunk.w;
    }
    // reduce across the 8 lanes sharing each chunk id (strides 16, 8, 4)
#pragma unroll
    for (int off = 16; off >= 4; off >>= 1) {
        acc.x += __shfl_down_sync(0xFFFFFFFFu, acc.x, off);
        acc.y += __shfl_down_sync(0xFFFFFFFFu, acc.y, off);
        acc.z += __shfl_down_sync(0xFFFFFFFFu, acc.z, off);
        acc.w += __shfl_down_sync(0xFFFFFFFFu, acc.w, off);
    }

    if (lane < 4) {
        // regulator i == node i; normalize its row on the fly too
        float deni = g_den[b * NN + i];
        float invi = (deni > 0.0f) ? __frcp_rn(deni) : 0.0f;
        const float4* rr = reinterpret_cast<const float4*>(g_rep + (size_t)(b * NN + i) * DEN);
        float4 rv = rr[lane];   // chunk == lane for lane<4
        rv.x = rv.x * invi + bchunk.x;
        rv.y = rv.y * invi + bchunk.y;
        rv.z = rv.z * invi + bchunk.z;
        rv.w = rv.w * invi + bchunk.w;
        float4* op = reinterpret_cast<float4*>(out + (size_t)(b * NREG + i) * DEN);
        op[lane] = make_float4(rv.x * acc.x, rv.y * acc.y, rv.z * acc.z, rv.w * acc.w);
    }
}

// ---------------- launch ------------------------------------------------------
extern "C" void kernel_launch(void* const* d_in, const int* in_sizes, int n_in,
                              void* d_out, int out_size) {
    const float* fea      = (const float*)d_in[0];   // [B,N,64]
    const int*   ei       = (const int*)d_in[1];     // [B,2,E]
    const float* ea       = (const float*)d_in[2];   // [B,E,1]
    const float* W        = (const float*)d_in[3];   // [64,16]
    const float* att_src  = (const float*)d_in[4];   // [16]
    const float* att_dst  = (const float*)d_in[5];   // [16]
    const float* lin_edge = (const float*)d_in[6];   // [1,16]
    const float* att_edge = (const float*)d_in[7];   // [16]
    const float* bias     = (const float*)d_in[8];   // [16]
    float* out = (float*)d_out;                      // [B,NREG,16]

    (void)in_sizes; (void)n_in; (void)out_size;

    {
        int tot = BB * NN * 4;
        k_node<<<(tot + 255) / 256, 256>>>(fea, W, att_src, att_dst, lin_edge, att_edge);
    }
    {
        dim3 grid((EE + 255) / 256, BB);
        k_edge_fused<<<grid, 256>>>(ei, ea);
    }
    {
        int tot = BB * NREG;
        k_pool<<<(tot + POOL_WARPS - 1) / POOL_WARPS, POOL_WARPS * 32>>>(ei, bias, out);
    }
}